// round 1
// baseline (speedup 1.0000x reference)
#include <cuda_runtime.h>
#include <cuda_bf16.h>

// Problem constants
#define PB  16
#define PTV 128
#define PTH 64
#define PF  512
#define PH  512
#define PD  256

// Scratch (device globals; no allocation in kernel_launch)
__device__ float g_Wv[PB * PTV * PD];    // [b][t][d]
__device__ float g_Uhb[PB * PTH * PD];   // [b][s][d]  (U h + b)
__device__ float g_beta[PB * PTH * PTV]; // [b][s][t]

// ---------------------------------------------------------------------------
// SGEMM with optional bias: C[M,N] = A[M,K] * B[K,N] (+ bias[N])
// BM=BN=64, BK=16, 256 threads, 4x4 microtile.
// ---------------------------------------------------------------------------
#define BM 64
#define BN 64
#define BK 16

__global__ __launch_bounds__(256) void sgemm_bias_kernel(
    const float* __restrict__ A, const float* __restrict__ Bm,
    const float* __restrict__ bias, float* __restrict__ C,
    int M, int N, int K)
{
    __shared__ float As[BK][BM + 4];  // transposed A tile, padded
    __shared__ float Bs[BK][BN];

    const int tid = threadIdx.x;
    const int tx = tid & 15;        // 0..15 -> N direction
    const int ty = tid >> 4;        // 0..15 -> M direction
    const int row0 = blockIdx.x * BM;
    const int col0 = blockIdx.y * BN;

    // A-tile load mapping: thread loads float4 of A[row0 + tid/4][k0 + (tid%4)*4]
    const int a_m = tid >> 2;          // 0..63
    const int a_k = (tid & 3) << 2;    // 0,4,8,12
    // B-tile load mapping: thread loads float4 of B[k0 + tid/16][col0 + (tid%16)*4]
    const int b_k = tid >> 4;          // 0..15
    const int b_n = (tid & 15) << 2;   // 0..60

    float acc[4][4];
#pragma unroll
    for (int i = 0; i < 4; i++)
#pragma unroll
        for (int j = 0; j < 4; j++) acc[i][j] = 0.0f;

    for (int k0 = 0; k0 < K; k0 += BK) {
        float4 av = *reinterpret_cast<const float4*>(A + (size_t)(row0 + a_m) * K + k0 + a_k);
        As[a_k + 0][a_m] = av.x;
        As[a_k + 1][a_m] = av.y;
        As[a_k + 2][a_m] = av.z;
        As[a_k + 3][a_m] = av.w;

        float4 bv = *reinterpret_cast<const float4*>(Bm + (size_t)(k0 + b_k) * N + col0 + b_n);
        *reinterpret_cast<float4*>(&Bs[b_k][b_n]) = bv;

        __syncthreads();

#pragma unroll
        for (int k = 0; k < BK; k++) {
            float4 a4 = *reinterpret_cast<const float4*>(&As[k][ty << 2]);
            float4 b4 = *reinterpret_cast<const float4*>(&Bs[k][tx << 2]);
            float a[4] = {a4.x, a4.y, a4.z, a4.w};
            float b[4] = {b4.x, b4.y, b4.z, b4.w};
#pragma unroll
            for (int i = 0; i < 4; i++)
#pragma unroll
                for (int j = 0; j < 4; j++) acc[i][j] += a[i] * b[j];
        }
        __syncthreads();
    }

    // epilogue (vectorized, bias optional)
    float4 bias4 = make_float4(0.f, 0.f, 0.f, 0.f);
    if (bias != nullptr)
        bias4 = *reinterpret_cast<const float4*>(bias + col0 + (tx << 2));
#pragma unroll
    for (int i = 0; i < 4; i++) {
        int r = row0 + (ty << 2) + i;
        float4 out;
        out.x = acc[i][0] + bias4.x;
        out.y = acc[i][1] + bias4.y;
        out.z = acc[i][2] + bias4.z;
        out.w = acc[i][3] + bias4.w;
        *reinterpret_cast<float4*>(C + (size_t)r * N + col0 + (tx << 2)) = out;
    }
}

// ---------------------------------------------------------------------------
// Scores + softmax: beta[b][s][t] = softmax_t( sum_d tanh(Uhb[b,s,d] + Wv[b,t,d]) * w[d] )
// Grid: (TH/4, B); 256 threads (8 warps). Warp handles t = warp, warp+8, ...
// Lanes cover d (coalesced Wv reads). 4 s-values per CTA.
// ---------------------------------------------------------------------------
__device__ __forceinline__ float safe_tanh(float x) {
    // tanh(x) = 1 - 2/(exp(2x)+1); exact at saturation, ~1e-6 error
    float e = __expf(2.0f * x);
    return 1.0f - __fdividef(2.0f, e + 1.0f);
}

__global__ __launch_bounds__(256) void attn_scores_kernel(
    const float* __restrict__ Wv, const float* __restrict__ Uhb,
    const float* __restrict__ wvec, float* __restrict__ beta)
{
    const int b = blockIdx.y;
    const int s0 = blockIdx.x * 4;
    const int tid = threadIdx.x;
    const int lane = tid & 31;
    const int warp = tid >> 5;

    __shared__ float sw[PD];
    __shared__ float su[4][PD];
    __shared__ float q[4][PTV];

    if (tid < PD) sw[tid] = wvec[tid];
    for (int i = tid; i < 4 * PD; i += 256) {
        int s = i >> 8;
        int d = i & (PD - 1);
        su[s][d] = Uhb[((size_t)(b * PTH + s0 + s) << 8) + d];
    }
    __syncthreads();

    for (int t = warp; t < PTV; t += 8) {
        const float* wvrow = Wv + ((size_t)(b * PTV + t) << 8);
        float acc0 = 0.f, acc1 = 0.f, acc2 = 0.f, acc3 = 0.f;
#pragma unroll
        for (int c = 0; c < 8; c++) {
            int d = (c << 5) + lane;
            float wv = wvrow[d];
            float wd = sw[d];
            acc0 += safe_tanh(su[0][d] + wv) * wd;
            acc1 += safe_tanh(su[1][d] + wv) * wd;
            acc2 += safe_tanh(su[2][d] + wv) * wd;
            acc3 += safe_tanh(su[3][d] + wv) * wd;
        }
#pragma unroll
        for (int off = 16; off; off >>= 1) {
            acc0 += __shfl_xor_sync(0xffffffffu, acc0, off);
            acc1 += __shfl_xor_sync(0xffffffffu, acc1, off);
            acc2 += __shfl_xor_sync(0xffffffffu, acc2, off);
            acc3 += __shfl_xor_sync(0xffffffffu, acc3, off);
        }
        if (lane == 0) {
            q[0][t] = acc0; q[1][t] = acc1; q[2][t] = acc2; q[3][t] = acc3;
        }
    }
    __syncthreads();

    // softmax over t (128 values) — warp w < 4 handles s = w; 4 values/lane
    if (warp < 4) {
        const int s = warp;
        float v0 = q[s][lane];
        float v1 = q[s][lane + 32];
        float v2 = q[s][lane + 64];
        float v3 = q[s][lane + 96];
        float m = fmaxf(fmaxf(v0, v1), fmaxf(v2, v3));
#pragma unroll
        for (int off = 16; off; off >>= 1)
            m = fmaxf(m, __shfl_xor_sync(0xffffffffu, m, off));
        float e0 = __expf(v0 - m);
        float e1 = __expf(v1 - m);
        float e2 = __expf(v2 - m);
        float e3 = __expf(v3 - m);
        float ssum = e0 + e1 + e2 + e3;
#pragma unroll
        for (int off = 16; off; off >>= 1)
            ssum += __shfl_xor_sync(0xffffffffu, ssum, off);
        float inv = 1.0f / ssum;
        float* bout = beta + ((size_t)(b * PTH + s0 + s) << 7);
        bout[lane]      = e0 * inv;
        bout[lane + 32] = e1 * inv;
        bout[lane + 64] = e2 * inv;
        bout[lane + 96] = e3 * inv;
    }
}

// ---------------------------------------------------------------------------
// Context: u[b][s][f] = sum_t beta[b][s][t] * v[b][t][f]
// Grid: (F/128, B); 256 threads. beta[b] staged in smem (32KB).
// Thread (tid): f-group = tid&31 (float4), s-rows = (tid>>5)*8 .. +8.
// ---------------------------------------------------------------------------
__global__ __launch_bounds__(256) void context_kernel(
    const float* __restrict__ v, const float* __restrict__ beta,
    float* __restrict__ u)
{
    const int b = blockIdx.y;
    const int f0 = blockIdx.x * 128;
    const int tid = threadIdx.x;

    __shared__ float sb[PTH][PTV];  // 64 x 128 = 32KB

    {
        const float4* src = reinterpret_cast<const float4*>(beta + (size_t)b * PTH * PTV);
        float4* dst = reinterpret_cast<float4*>(&sb[0][0]);
        for (int i = tid; i < PTH * PTV / 4; i += 256) dst[i] = src[i];
    }
    __syncthreads();

    const int fg = tid & 31;
    const int srow = tid >> 5;      // 0..7
    const int f = f0 + (fg << 2);

    float4 acc[8];
#pragma unroll
    for (int s = 0; s < 8; s++) acc[s] = make_float4(0.f, 0.f, 0.f, 0.f);

    const float* vbase = v + (size_t)(b * PTV) * PF + f;
    for (int t = 0; t < PTV; t++) {
        float4 vr = *reinterpret_cast<const float4*>(vbase + (size_t)t * PF);
#pragma unroll
        for (int s = 0; s < 8; s++) {
            float bb = sb[(srow << 3) + s][t];
            acc[s].x += bb * vr.x;
            acc[s].y += bb * vr.y;
            acc[s].z += bb * vr.z;
            acc[s].w += bb * vr.w;
        }
    }
#pragma unroll
    for (int s = 0; s < 8; s++) {
        *reinterpret_cast<float4*>(u + (size_t)(b * PTH + (srow << 3) + s) * PF + f) = acc[s];
    }
}

// ---------------------------------------------------------------------------
// kernel_launch
// Inputs: v [16,128,512], h [16,64,512], W [512,256], U [512,256], b [256], w [256,1]
// Output: u [16,64,512] float32
// ---------------------------------------------------------------------------
extern "C" void kernel_launch(void* const* d_in, const int* in_sizes, int n_in,
                              void* d_out, int out_size)
{
    const float* v    = (const float*)d_in[0];
    const float* h    = (const float*)d_in[1];
    const float* W    = (const float*)d_in[2];
    const float* U    = (const float*)d_in[3];
    const float* bvec = (const float*)d_in[4];
    const float* wvec = (const float*)d_in[5];
    float* out = (float*)d_out;

    float* wv_ptr;   cudaGetSymbolAddress((void**)&wv_ptr,  g_Wv);
    float* uhb_ptr;  cudaGetSymbolAddress((void**)&uhb_ptr, g_Uhb);
    float* beta_ptr; cudaGetSymbolAddress((void**)&beta_ptr, g_beta);

    // Wv = v @ W      : M=2048, N=256, K=512
    sgemm_bias_kernel<<<dim3((PB * PTV) / BM, PD / BN), 256>>>(
        v, W, nullptr, wv_ptr, PB * PTV, PD, PF);
    // Uhb = h @ U + b : M=1024, N=256, K=512
    sgemm_bias_kernel<<<dim3((PB * PTH) / BM, PD / BN), 256>>>(
        h, U, bvec, uhb_ptr, PB * PTH, PD, PH);
    // scores + softmax -> beta
    attn_scores_kernel<<<dim3(PTH / 4, PB), 256>>>(wv_ptr, uhb_ptr, wvec, beta_ptr);
    // context u = beta @ v
    context_kernel<<<dim3(PF / 128, PB), 256>>>(v, beta_ptr, out);
}

// round 3
// speedup vs baseline: 1.3064x; 1.3064x over previous
#include <cuda_runtime.h>
#include <cuda_bf16.h>

// Problem constants
#define PB  16
#define PTV 128
#define PTH 64
#define PF  512
#define PH  512
#define PD  256

// 2*log2(e): fold into GEMM epilogue so tanh arg feeds ex2 directly
#define C2LOG2E 2.8853900817779268f

// Scratch (device globals; no allocation in kernel_launch)
__device__ float g_Wv[PB * PTV * PD];    // [b][t][d]  (v@W) * 2log2e
__device__ float g_Uhb[PB * PTH * PD];   // [b][s][d]  (h@U + b) * 2log2e

__device__ __forceinline__ float ex2f(float x) {
    float r; asm("ex2.approx.ftz.f32 %0, %1;" : "=f"(r) : "f"(x)); return r;
}
__device__ __forceinline__ float rcpf(float x) {
    float r; asm("rcp.approx.ftz.f32 %0, %1;" : "=f"(r) : "f"(x)); return r;
}

// ---------------------------------------------------------------------------
// Fused dual SGEMM (one launch, 192 CTAs):
//   bid <  128 : Wv  = (v @ W) * C          tiles of M=2048, N=256
//   bid >= 128 : Uhb = (h @ U + b) * C      tiles of M=1024, N=256
// BM=BN=64, BK=16, 256 threads, 4x4 microtile.
// ---------------------------------------------------------------------------
#define BM 64
#define BN 64
#define BK 16

__global__ __launch_bounds__(256) void dual_sgemm_kernel(
    const float* __restrict__ v, const float* __restrict__ h,
    const float* __restrict__ W, const float* __restrict__ U,
    const float* __restrict__ bias)
{
    __shared__ float As[BK][BM + 4];
    __shared__ float Bs[BK][BN];

    const int tid = threadIdx.x;
    int bid = blockIdx.x;

    const float* A;
    const float* Bm;
    const float* bvec;
    float* C;
    int row0, col0;
    if (bid < 128) {
        A = v; Bm = W; bvec = nullptr; C = g_Wv;
        row0 = (bid >> 2) * BM;          // 32 M-tiles
        col0 = (bid & 3) * BN;           // 4 N-tiles
    } else {
        bid -= 128;
        A = h; Bm = U; bvec = bias; C = g_Uhb;
        row0 = (bid >> 2) * BM;          // 16 M-tiles
        col0 = (bid & 3) * BN;
    }
    const int K = 512;
    const int N = PD;

    const int tx = tid & 15;
    const int ty = tid >> 4;
    const int a_m = tid >> 2;
    const int a_k = (tid & 3) << 2;
    const int b_k = tid >> 4;
    const int b_n = (tid & 15) << 2;

    float acc[4][4];
#pragma unroll
    for (int i = 0; i < 4; i++)
#pragma unroll
        for (int j = 0; j < 4; j++) acc[i][j] = 0.0f;

    for (int k0 = 0; k0 < K; k0 += BK) {
        float4 av = *reinterpret_cast<const float4*>(A + (size_t)(row0 + a_m) * K + k0 + a_k);
        As[a_k + 0][a_m] = av.x;
        As[a_k + 1][a_m] = av.y;
        As[a_k + 2][a_m] = av.z;
        As[a_k + 3][a_m] = av.w;

        float4 bv = *reinterpret_cast<const float4*>(Bm + (size_t)(k0 + b_k) * N + col0 + b_n);
        *reinterpret_cast<float4*>(&Bs[b_k][b_n]) = bv;

        __syncthreads();

#pragma unroll
        for (int k = 0; k < BK; k++) {
            float4 a4 = *reinterpret_cast<const float4*>(&As[k][ty << 2]);
            float4 b4 = *reinterpret_cast<const float4*>(&Bs[k][tx << 2]);
            float a[4] = {a4.x, a4.y, a4.z, a4.w};
            float b[4] = {b4.x, b4.y, b4.z, b4.w};
#pragma unroll
            for (int i = 0; i < 4; i++)
#pragma unroll
                for (int j = 0; j < 4; j++) acc[i][j] += a[i] * b[j];
        }
        __syncthreads();
    }

    float4 bias4 = make_float4(0.f, 0.f, 0.f, 0.f);
    if (bvec != nullptr)
        bias4 = *reinterpret_cast<const float4*>(bvec + col0 + (tx << 2));
#pragma unroll
    for (int i = 0; i < 4; i++) {
        int r = row0 + (ty << 2) + i;
        float4 out;
        out.x = (acc[i][0] + bias4.x) * C2LOG2E;
        out.y = (acc[i][1] + bias4.y) * C2LOG2E;
        out.z = (acc[i][2] + bias4.z) * C2LOG2E;
        out.w = (acc[i][3] + bias4.w) * C2LOG2E;
        *reinterpret_cast<float4*>(C + (size_t)r * N + col0 + (tx << 2)) = out;
    }
}

// ---------------------------------------------------------------------------
// Fused scores + softmax + context.
// Grid (TH/4=16, B=16) = 256 CTAs, 256 threads.
// Phase 1: q[s][t] = -2 * sum_d w[d] * rcp(exp2(Uhb_s[s,d] + Wv_s[t,d]) + 1)
//          (softmax shift-invariance absorbs the +sum(w) constant)
// Phase 2: softmax over t -> sbeta[4][128] in smem
// Phase 3: u[b][s0+i][:] = sum_t sbeta[i][t] * v[b][t][:]
//          threads: f4 = tid&127 (float4 col), th = tid>>7 (t-half); smem combine
// ---------------------------------------------------------------------------
__global__ __launch_bounds__(256) void attn_fused_kernel(
    const float* __restrict__ v, const float* __restrict__ wvec,
    float* __restrict__ u)
{
    const int b = blockIdx.y;
    const int s0 = blockIdx.x * 4;
    const int tid = threadIdx.x;
    const int lane = tid & 31;
    const int warp = tid >> 5;

    __shared__ float sw[PD];
    __shared__ float su[4][PD];
    __shared__ float q[4][PTV];
    __shared__ float sbeta[4][PTV];
    __shared__ float4 spart[4][PTV];

    if (tid < PD) sw[tid] = wvec[tid];
    for (int i = tid; i < 4 * PD; i += 256) {
        int s = i >> 8;
        int d = i & (PD - 1);
        su[s][d] = g_Uhb[((size_t)(b * PTH + s0 + s) << 8) + d];
    }
    __syncthreads();

    // ---- Phase 1: scores ----
    for (int t = warp; t < PTV; t += 8) {
        const float* wvrow = g_Wv + ((size_t)(b * PTV + t) << 8);
        float p0 = 0.f, p1 = 0.f, p2 = 0.f, p3 = 0.f;
#pragma unroll
        for (int c = 0; c < 8; c++) {
            int d = (c << 5) + lane;
            float wv = wvrow[d];
            float wd = sw[d];
            p0 += wd * rcpf(ex2f(su[0][d] + wv) + 1.0f);
            p1 += wd * rcpf(ex2f(su[1][d] + wv) + 1.0f);
            p2 += wd * rcpf(ex2f(su[2][d] + wv) + 1.0f);
            p3 += wd * rcpf(ex2f(su[3][d] + wv) + 1.0f);
        }
#pragma unroll
        for (int off = 16; off; off >>= 1) {
            p0 += __shfl_xor_sync(0xffffffffu, p0, off);
            p1 += __shfl_xor_sync(0xffffffffu, p1, off);
            p2 += __shfl_xor_sync(0xffffffffu, p2, off);
            p3 += __shfl_xor_sync(0xffffffffu, p3, off);
        }
        if (lane == 0) {
            q[0][t] = -2.0f * p0;
            q[1][t] = -2.0f * p1;
            q[2][t] = -2.0f * p2;
            q[3][t] = -2.0f * p3;
        }
    }
    __syncthreads();

    // ---- Phase 2: softmax over t (warps 0..3, s = warp) ----
    if (warp < 4) {
        const int s = warp;
        float v0 = q[s][lane];
        float v1 = q[s][lane + 32];
        float v2 = q[s][lane + 64];
        float v3 = q[s][lane + 96];
        float m = fmaxf(fmaxf(v0, v1), fmaxf(v2, v3));
#pragma unroll
        for (int off = 16; off; off >>= 1)
            m = fmaxf(m, __shfl_xor_sync(0xffffffffu, m, off));
        float e0 = __expf(v0 - m);
        float e1 = __expf(v1 - m);
        float e2 = __expf(v2 - m);
        float e3 = __expf(v3 - m);
        float ssum = e0 + e1 + e2 + e3;
#pragma unroll
        for (int off = 16; off; off >>= 1)
            ssum += __shfl_xor_sync(0xffffffffu, ssum, off);
        float inv = 1.0f / ssum;
        sbeta[s][lane]      = e0 * inv;
        sbeta[s][lane + 32] = e1 * inv;
        sbeta[s][lane + 64] = e2 * inv;
        sbeta[s][lane + 96] = e3 * inv;
    }
    __syncthreads();

    // ---- Phase 3: context ----
    const int f4 = tid & 127;          // float4 column (512 floats = 128 cols)
    const int th = tid >> 7;           // t-half: 0 -> [0,64), 1 -> [64,128)

    float4 acc0 = make_float4(0.f, 0.f, 0.f, 0.f);
    float4 acc1 = make_float4(0.f, 0.f, 0.f, 0.f);
    float4 acc2 = make_float4(0.f, 0.f, 0.f, 0.f);
    float4 acc3 = make_float4(0.f, 0.f, 0.f, 0.f);

    const float* vbase = v + ((size_t)(b * PTV + th * 64) * PF) + (f4 << 2);
#pragma unroll 4
    for (int t = 0; t < 64; t++) {
        float4 vr = *reinterpret_cast<const float4*>(vbase + (size_t)t * PF);
        int tt = th * 64 + t;
        float b0 = sbeta[0][tt];
        float b1 = sbeta[1][tt];
        float b2 = sbeta[2][tt];
        float b3 = sbeta[3][tt];
        acc0.x += b0 * vr.x; acc0.y += b0 * vr.y; acc0.z += b0 * vr.z; acc0.w += b0 * vr.w;
        acc1.x += b1 * vr.x; acc1.y += b1 * vr.y; acc1.z += b1 * vr.z; acc1.w += b1 * vr.w;
        acc2.x += b2 * vr.x; acc2.y += b2 * vr.y; acc2.z += b2 * vr.z; acc2.w += b2 * vr.w;
        acc3.x += b3 * vr.x; acc3.y += b3 * vr.y; acc3.z += b3 * vr.z; acc3.w += b3 * vr.w;
    }

    if (th == 1) {
        spart[0][f4] = acc0;
        spart[1][f4] = acc1;
        spart[2][f4] = acc2;
        spart[3][f4] = acc3;
    }
    __syncthreads();
    if (th == 0) {
        float4 o0 = spart[0][f4];
        float4 o1 = spart[1][f4];
        float4 o2 = spart[2][f4];
        float4 o3 = spart[3][f4];
        o0.x += acc0.x; o0.y += acc0.y; o0.z += acc0.z; o0.w += acc0.w;
        o1.x += acc1.x; o1.y += acc1.y; o1.z += acc1.z; o1.w += acc1.w;
        o2.x += acc2.x; o2.y += acc2.y; o2.z += acc2.z; o2.w += acc2.w;
        o3.x += acc3.x; o3.y += acc3.y; o3.z += acc3.z; o3.w += acc3.w;
        float* ub = u + (size_t)(b * PTH + s0) * PF + (f4 << 2);
        *reinterpret_cast<float4*>(ub)            = o0;
        *reinterpret_cast<float4*>(ub + PF)       = o1;
        *reinterpret_cast<float4*>(ub + 2 * PF)   = o2;
        *reinterpret_cast<float4*>(ub + 3 * PF)   = o3;
    }
}

// ---------------------------------------------------------------------------
// kernel_launch
// Inputs: v [16,128,512], h [16,64,512], W [512,256], U [512,256], b [256], w [256,1]
// Output: u [16,64,512] float32
// ---------------------------------------------------------------------------
extern "C" void kernel_launch(void* const* d_in, const int* in_sizes, int n_in,
                              void* d_out, int out_size)
{
    const float* v    = (const float*)d_in[0];
    const float* h    = (const float*)d_in[1];
    const float* W    = (const float*)d_in[2];
    const float* U    = (const float*)d_in[3];
    const float* bvec = (const float*)d_in[4];
    const float* wvec = (const float*)d_in[5];
    float* out = (float*)d_out;

    // Fused GEMMs: 128 CTAs (v@W) + 64 CTAs (h@U + b), one launch
    dual_sgemm_kernel<<<192, 256>>>(v, h, W, U, bvec);
    // Fused scores + softmax + context
    attn_fused_kernel<<<dim3(PTH / 4, PB), 256>>>(v, wvec, out);
}

// round 4
// speedup vs baseline: 1.4120x; 1.0808x over previous
#include <cuda_runtime.h>
#include <cuda_bf16.h>

// Problem constants
#define PB  16
#define PTV 128
#define PTH 64
#define PF  512
#define PH  512
#define PD  256

// Scratch (device globals; no allocation in kernel_launch)
__device__ float g_WvT[PB * PD * PTV];   // [b][d][t]  (v@W) transposed
__device__ float g_Uhb[PB * PTH * PD];   // [b][s][d]  (h@U + b)
__device__ float g_beta[PB * PTH * PTV]; // [b][s][t]

__device__ __forceinline__ float tanh_approx(float x) {
    float r; asm("tanh.approx.f32 %0, %1;" : "=f"(r) : "f"(x)); return r;
}

// ---------------------------------------------------------------------------
// Fused dual SGEMM (one launch, 192 CTAs):
//   bid <  128 : WvT[b][d][t] = (v @ W)^T per batch   (transposed epilogue)
//   bid >= 128 : Uhb[b][s][d] = h @ U + b
// BM=BN=64, BK=16, 256 threads, 4x4 microtile.
// ---------------------------------------------------------------------------
#define BM 64
#define BN 64
#define BK 16

__global__ __launch_bounds__(256) void dual_sgemm_kernel(
    const float* __restrict__ v, const float* __restrict__ h,
    const float* __restrict__ W, const float* __restrict__ U,
    const float* __restrict__ bias)
{
    __shared__ float As[BK][BM + 4];
    __shared__ float Bs[BK][BN];

    const int tid = threadIdx.x;
    int bid = blockIdx.x;

    const float* A;
    const float* Bm;
    int row0, col0;
    bool is_wv;
    if (bid < 128) {
        A = v; Bm = W; is_wv = true;
        row0 = (bid >> 2) * BM;          // 32 M-tiles (M=2048)
        col0 = (bid & 3) * BN;
    } else {
        bid -= 128;
        A = h; Bm = U; is_wv = false;
        row0 = (bid >> 2) * BM;          // 16 M-tiles (M=1024)
        col0 = (bid & 3) * BN;
    }
    const int K = 512;
    const int N = PD;

    const int tx = tid & 15;
    const int ty = tid >> 4;
    const int a_m = tid >> 2;
    const int a_k = (tid & 3) << 2;
    const int b_k = tid >> 4;
    const int b_n = (tid & 15) << 2;

    float acc[4][4];
#pragma unroll
    for (int i = 0; i < 4; i++)
#pragma unroll
        for (int j = 0; j < 4; j++) acc[i][j] = 0.0f;

    for (int k0 = 0; k0 < K; k0 += BK) {
        float4 av = *reinterpret_cast<const float4*>(A + (size_t)(row0 + a_m) * K + k0 + a_k);
        As[a_k + 0][a_m] = av.x;
        As[a_k + 1][a_m] = av.y;
        As[a_k + 2][a_m] = av.z;
        As[a_k + 3][a_m] = av.w;

        float4 bv = *reinterpret_cast<const float4*>(Bm + (size_t)(k0 + b_k) * N + col0 + b_n);
        *reinterpret_cast<float4*>(&Bs[b_k][b_n]) = bv;

        __syncthreads();

#pragma unroll
        for (int k = 0; k < BK; k++) {
            float4 a4 = *reinterpret_cast<const float4*>(&As[k][ty << 2]);
            float4 b4 = *reinterpret_cast<const float4*>(&Bs[k][tx << 2]);
            float a[4] = {a4.x, a4.y, a4.z, a4.w};
            float b[4] = {b4.x, b4.y, b4.z, b4.w};
#pragma unroll
            for (int i = 0; i < 4; i++)
#pragma unroll
                for (int j = 0; j < 4; j++) acc[i][j] += a[i] * b[j];
        }
        __syncthreads();
    }

    if (is_wv) {
        // Transposed write: WvT[b][d][t]. Consecutive i (M rows) = consecutive t.
        const int b = row0 >> 7;          // 128 t-rows per batch
        const int t0 = (row0 & 127) + (ty << 2);
#pragma unroll
        for (int j = 0; j < 4; j++) {
            int d = col0 + (tx << 2) + j;
            float4 out = make_float4(acc[0][j], acc[1][j], acc[2][j], acc[3][j]);
            *reinterpret_cast<float4*>(g_WvT + (((size_t)(b << 8) + d) << 7) + t0) = out;
        }
    } else {
        float4 bias4 = *reinterpret_cast<const float4*>(bias + col0 + (tx << 2));
#pragma unroll
        for (int i = 0; i < 4; i++) {
            int r = row0 + (ty << 2) + i;
            float4 out;
            out.x = acc[i][0] + bias4.x;
            out.y = acc[i][1] + bias4.y;
            out.z = acc[i][2] + bias4.z;
            out.w = acc[i][3] + bias4.w;
            *reinterpret_cast<float4*>(g_Uhb + (size_t)r * N + col0 + (tx << 2)) = out;
        }
    }
}

// ---------------------------------------------------------------------------
// Scores + softmax. Grid (TH/2=32, B=16) = 512 CTAs, 256 threads.
// Thread = (si = tid>>7 in [0,2), t = tid&127). Serial d-loop, no reductions
// in the hot loop: q = sum_d w[d] * tanh(Uhb[s,d] + WvT[b,d,t]).
// Then softmax over t (4 warps per s, smem-combined) -> g_beta[b][s][t].
// ---------------------------------------------------------------------------
__global__ __launch_bounds__(256) void scores_kernel(
    const float* __restrict__ wvec, float* __restrict__ beta)
{
    const int b = blockIdx.y;
    const int s0 = blockIdx.x * 2;
    const int tid = threadIdx.x;
    const int t = tid & 127;
    const int si = tid >> 7;

    __shared__ float su[2][PD];
    __shared__ float sw[PD];
    __shared__ float rmax[2][4];
    __shared__ float rsum[2][4];

    if (tid < PD) sw[tid] = wvec[tid];
#pragma unroll
    for (int i = tid; i < 2 * PD; i += 256)
        su[i >> 8][i & 255] = g_Uhb[((size_t)(b * PTH + s0 + (i >> 8)) << 8) + (i & 255)];
    __syncthreads();

    const float* wvt = g_WvT + ((size_t)b << 15) + t;   // stride 128 per d

    float acc = 0.0f;
#pragma unroll 8
    for (int d = 0; d < PD; d++) {
        float x = su[si][d] + wvt[(size_t)d << 7];
        acc += sw[d] * tanh_approx(x);
    }

    // softmax over t: 4 warps per s-slice
    const int lane = t & 31;
    const int wq = t >> 5;

    float m = acc;
#pragma unroll
    for (int off = 16; off; off >>= 1)
        m = fmaxf(m, __shfl_xor_sync(0xffffffffu, m, off));
    if (lane == 0) rmax[si][wq] = m;
    __syncthreads();
    m = fmaxf(fmaxf(rmax[si][0], rmax[si][1]), fmaxf(rmax[si][2], rmax[si][3]));

    float e = __expf(acc - m);
    float ssum = e;
#pragma unroll
    for (int off = 16; off; off >>= 1)
        ssum += __shfl_xor_sync(0xffffffffu, ssum, off);
    if (lane == 0) rsum[si][wq] = ssum;
    __syncthreads();
    float total = (rsum[si][0] + rsum[si][1]) + (rsum[si][2] + rsum[si][3]);

    beta[((size_t)(b * PTH + s0 + si) << 7) + t] = e * (1.0f / total);
}

// ---------------------------------------------------------------------------
// Context: u[b][s][f] = sum_t beta[b][s][t] * v[b][t][f]
// Grid (F/128=4, TH/16=4, B=16) = 256 CTAs, 256 threads.
// Thread: f4 = tid&31 (float4 col), row = tid>>5 handles s = 2*row, 2*row+1.
// beta tile (16 s x 128 t) staged in 8KB smem.
// ---------------------------------------------------------------------------
__global__ __launch_bounds__(256) void context_kernel(
    const float* __restrict__ v, const float* __restrict__ beta,
    float* __restrict__ u)
{
    const int b = blockIdx.z;
    const int s0 = blockIdx.y * 16;
    const int f0 = blockIdx.x * 128;
    const int tid = threadIdx.x;

    __shared__ float sb[16][PTV];   // 8KB

    {
        const float4* src = reinterpret_cast<const float4*>(
            beta + ((size_t)(b * PTH + s0) << 7));
        float4* dst = reinterpret_cast<float4*>(&sb[0][0]);
#pragma unroll
        for (int i = tid; i < 16 * PTV / 4; i += 256) dst[i] = src[i];
    }
    __syncthreads();

    const int f4 = tid & 31;
    const int row = tid >> 5;           // 0..7
    const int sA = row << 1;
    const int sB = sA + 1;

    float4 a0 = make_float4(0.f, 0.f, 0.f, 0.f);
    float4 a1 = make_float4(0.f, 0.f, 0.f, 0.f);

    const float* vb = v + (size_t)(b * PTV) * PF + f0 + (f4 << 2);
#pragma unroll 4
    for (int tt = 0; tt < PTV; tt++) {
        float4 vr = *reinterpret_cast<const float4*>(vb + (size_t)tt * PF);
        float b0 = sb[sA][tt];
        float b1 = sb[sB][tt];
        a0.x += b0 * vr.x; a0.y += b0 * vr.y; a0.z += b0 * vr.z; a0.w += b0 * vr.w;
        a1.x += b1 * vr.x; a1.y += b1 * vr.y; a1.z += b1 * vr.z; a1.w += b1 * vr.w;
    }

    float* ub = u + (size_t)(b * PTH + s0 + sA) * PF + f0 + (f4 << 2);
    *reinterpret_cast<float4*>(ub)      = a0;
    *reinterpret_cast<float4*>(ub + PF) = a1;
}

// ---------------------------------------------------------------------------
// kernel_launch
// Inputs: v [16,128,512], h [16,64,512], W [512,256], U [512,256], b [256], w [256,1]
// Output: u [16,64,512] float32
// ---------------------------------------------------------------------------
extern "C" void kernel_launch(void* const* d_in, const int* in_sizes, int n_in,
                              void* d_out, int out_size)
{
    const float* v    = (const float*)d_in[0];
    const float* h    = (const float*)d_in[1];
    const float* W    = (const float*)d_in[2];
    const float* U    = (const float*)d_in[3];
    const float* bvec = (const float*)d_in[4];
    const float* wvec = (const float*)d_in[5];
    float* out = (float*)d_out;

    float* beta_ptr; cudaGetSymbolAddress((void**)&beta_ptr, g_beta);

    // Fused GEMMs: 128 CTAs (v@W -> WvT) + 64 CTAs (h@U + b), one launch
    dual_sgemm_kernel<<<192, 256>>>(v, h, W, U, bvec);
    // Scores + softmax -> beta
    scores_kernel<<<dim3(PTH / 2, PB), 256>>>(wvec, beta_ptr);
    // Context u = beta @ v
    context_kernel<<<dim3(PF / 128, PTH / 16, PB), 256>>>(v, beta_ptr, out);
}

// round 6
// speedup vs baseline: 1.9117x; 1.3539x over previous
#include <cuda_runtime.h>
#include <cuda_bf16.h>
#include <cstdint>

// Problem constants
#define PB  16
#define PTV 128
#define PTH 64
#define PF  512
#define PH  512
#define PD  256
#define KDIM 512

// GEMM geometry: rows = [v (2048) ; h (1024)] = 3072 = 48 tiles of 64
// N = 256 = 4 tiles of 64. K = 512 = 32 iters of 16.
#define MTILES 48
#define KITERS 32

// ---------------------------------------------------------------------------
// Device scratch
// ---------------------------------------------------------------------------
// A fragments, per-lane packed for mma.sync m16n8k16 bf16:
//   [tile 48][kit 32][mfrag 4][hl 2][lane 32] : uint4 = regs {a01, a23, a45, a67}
__device__ uint4 g_Afrag[MTILES * KITERS * 4 * 2 * 32];
// B fragments: [mat 2][kit 32][nfrag 32][lane 32] : uint4 = {bhi01, bhi23, blo01, blo23}
__device__ uint4 g_Bfrag[2 * KITERS * 32 * 32];

__device__ float g_WvT[PB * PD * PTV];   // [b][d][t]
__device__ float g_Uhb[PB * PTH * PD];   // [b][s][d]
__device__ float g_beta[PB * PTH * PTV]; // [b][s][t]

__device__ __forceinline__ float tanh_approx(float x) {
    float r; asm("tanh.approx.f32 %0, %1;" : "=f"(r) : "f"(x)); return r;
}
__device__ __forceinline__ uint32_t pack2(__nv_bfloat16 a, __nv_bfloat16 b) {
    return (uint32_t)__bfloat16_as_ushort(a) | ((uint32_t)__bfloat16_as_ushort(b) << 16);
}
__device__ __forceinline__ void split_bf16(float x, __nv_bfloat16& hi, __nv_bfloat16& lo) {
    hi = __float2bfloat16(x);
    lo = __float2bfloat16(x - __bfloat162float(hi));
}

__device__ __forceinline__ void mma_bf16(float* c, uint32_t a0, uint32_t a1, uint32_t a2, uint32_t a3,
                                         uint32_t b0, uint32_t b1) {
    asm volatile(
        "mma.sync.aligned.m16n8k16.row.col.f32.bf16.bf16.f32 "
        "{%0,%1,%2,%3}, {%4,%5,%6,%7}, {%8,%9}, {%0,%1,%2,%3};"
        : "+f"(c[0]), "+f"(c[1]), "+f"(c[2]), "+f"(c[3])
        : "r"(a0), "r"(a1), "r"(a2), "r"(a3), "r"(b0), "r"(b1));
}

// ---------------------------------------------------------------------------
// Prep kernel: build per-lane fragment images (hi/lo bf16 split).
// A items: (tile 48, kit 32, mfrag 4, lane 32) = 196608 threads (each writes hi+lo)
// B items: (mat 2, kit 32, nfrag 32, lane 32)  = 65536 threads
// grid = 1024 x 256.
// ---------------------------------------------------------------------------
__global__ __launch_bounds__(256) void prep_kernel(
    const float* __restrict__ v, const float* __restrict__ h,
    const float* __restrict__ W, const float* __restrict__ U)
{
    int gid = blockIdx.x * 256 + threadIdx.x;
    if (gid < 196608) {
        // A fragment: rows r0 = tile*64 + mf*16 + (lane>>2), r1 = r0+8
        //             cols k0 = kit*16 + (lane&3)*2, k8 = k0+8
        int lane = gid & 31;
        int mf   = (gid >> 5) & 3;
        int kit  = (gid >> 7) & 31;
        int tile = gid >> 12;

        int rloc = tile * 64 + mf * 16 + (lane >> 2);
        const float* r0p;
        const float* r1p;
        if (tile < 32) {
            r0p = v + (size_t)rloc * KDIM;
        } else {
            r0p = h + (size_t)(rloc - 2048) * KDIM;
        }
        r1p = r0p + 8 * KDIM;
        int k0 = kit * 16 + (lane & 3) * 2;

        float2 x00 = *reinterpret_cast<const float2*>(r0p + k0);
        float2 x10 = *reinterpret_cast<const float2*>(r1p + k0);
        float2 x08 = *reinterpret_cast<const float2*>(r0p + k0 + 8);
        float2 x18 = *reinterpret_cast<const float2*>(r1p + k0 + 8);

        __nv_bfloat16 h00a, l00a, h00b, l00b, h10a, l10a, h10b, l10b;
        __nv_bfloat16 h08a, l08a, h08b, l08b, h18a, l18a, h18b, l18b;
        split_bf16(x00.x, h00a, l00a); split_bf16(x00.y, h00b, l00b);
        split_bf16(x10.x, h10a, l10a); split_bf16(x10.y, h10b, l10b);
        split_bf16(x08.x, h08a, l08a); split_bf16(x08.y, h08b, l08b);
        split_bf16(x18.x, h18a, l18a); split_bf16(x18.y, h18b, l18b);

        uint4 vh, vl;
        vh.x = pack2(h00a, h00b); vh.y = pack2(h10a, h10b);
        vh.z = pack2(h08a, h08b); vh.w = pack2(h18a, h18b);
        vl.x = pack2(l00a, l00b); vl.y = pack2(l10a, l10b);
        vl.z = pack2(l08a, l08b); vl.w = pack2(l18a, l18b);

        size_t base = ((((size_t)tile * KITERS + kit) * 4 + mf) * 2) * 32 + lane;
        g_Afrag[base]      = vh;
        g_Afrag[base + 32] = vl;
    } else if (gid < 262144) {
        // B fragment: col n = nfrag*8 + (lane>>2); rows k0 = kit*16 + (lane&3)*2, +1, +8, +9
        int item = gid - 196608;
        int lane = item & 31;
        int nf   = (item >> 5) & 31;
        int kit  = (item >> 10) & 31;
        int mat  = item >> 15;                 // 0 = W, 1 = U

        const float* Bsrc = mat ? U : W;
        int n = nf * 8 + (lane >> 2);
        int k0 = kit * 16 + (lane & 3) * 2;

        float xa = Bsrc[(size_t)(k0 + 0) * PD + n];
        float xb = Bsrc[(size_t)(k0 + 1) * PD + n];
        float xc = Bsrc[(size_t)(k0 + 8) * PD + n];
        float xd = Bsrc[(size_t)(k0 + 9) * PD + n];

        __nv_bfloat16 ha, la, hb, lb, hc, lc, hd, ld;
        split_bf16(xa, ha, la); split_bf16(xb, hb, lb);
        split_bf16(xc, hc, lc); split_bf16(xd, hd, ld);

        uint4 out;
        out.x = pack2(ha, hb);   // bhi reg0
        out.y = pack2(hc, hd);   // bhi reg1
        out.z = pack2(la, lb);   // blo reg0
        out.w = pack2(lc, ld);   // blo reg1
        g_Bfrag[(((size_t)mat * KITERS + kit) * 32 + nf) * 32 + lane] = out;
    }
}

// ---------------------------------------------------------------------------
// bf16 split-float MMA GEMM. 192 CTAs x 128 threads (4 warps).
// CTA: 64 rows x 64 cols. Warp: 32x32 (mfrags 2 x nfrags 4).
// D = Ahi*Bhi + Ahi*Blo + Alo*Bhi, fp32 accum. 24 HMMA per k-iter.
// Epilogue: v-tiles -> g_WvT transposed (padded smem bounce);
//           h-tiles -> g_Uhb + bias (direct float2 stores).
// ---------------------------------------------------------------------------
__global__ __launch_bounds__(128) void mma_gemm_kernel(const float* __restrict__ bias)
{
    const int tile  = blockIdx.x >> 2;     // 0..47
    const int ntile = blockIdx.x & 3;      // 0..3
    const int tid   = threadIdx.x;
    const int lane  = tid & 31;
    const int wid   = tid >> 5;
    const int wm    = wid >> 1;            // 0..1 (M half)
    const int wn    = wid & 1;             // 0..1 (N half)
    const bool is_v = tile < 32;

    __shared__ float st[64][72];           // transpose bounce (v-tiles), padded

    float acc[2][4][4];
#pragma unroll
    for (int mf = 0; mf < 2; mf++)
#pragma unroll
        for (int nf = 0; nf < 4; nf++)
#pragma unroll
            for (int r = 0; r < 4; r++) acc[mf][nf][r] = 0.0f;

    // A base: [tile][kit][mfrag = wm*2 + mf][hl][lane]
    const uint4* Ab = g_Afrag + (((size_t)tile * KITERS * 4 + wm * 2) * 2) * 32 + lane;
    // B base: [mat][kit][nfrag = ntile*8 + wn*4 + nf][lane]
    const uint4* Bb = g_Bfrag + ((size_t)(is_v ? 0 : 1) * KITERS * 32 + (ntile * 8 + wn * 4)) * 32 + lane;

#pragma unroll 2
    for (int kit = 0; kit < KITERS; kit++) {
        const uint4* Ak = Ab + (size_t)kit * 256;     // 4*2*32 uint4 per kit
        const uint4* Bk = Bb + (size_t)kit * 1024;    // 32*32 uint4 per kit
        uint4 A0h = Ak[0];
        uint4 A0l = Ak[32];
        uint4 A1h = Ak[64];
        uint4 A1l = Ak[96];
        uint4 B0 = Bk[0];
        uint4 B1 = Bk[32];
        uint4 B2 = Bk[64];
        uint4 B3 = Bk[96];

        uint4 Bf[4] = {B0, B1, B2, B3};
        uint4 Ah[2] = {A0h, A1h};
        uint4 Al[2] = {A0l, A1l};
#pragma unroll
        for (int mf = 0; mf < 2; mf++) {
#pragma unroll
            for (int nf = 0; nf < 4; nf++) {
                mma_bf16(acc[mf][nf], Ah[mf].x, Ah[mf].y, Ah[mf].z, Ah[mf].w, Bf[nf].x, Bf[nf].y);
                mma_bf16(acc[mf][nf], Ah[mf].x, Ah[mf].y, Ah[mf].z, Ah[mf].w, Bf[nf].z, Bf[nf].w);
                mma_bf16(acc[mf][nf], Al[mf].x, Al[mf].y, Al[mf].z, Al[mf].w, Bf[nf].x, Bf[nf].y);
            }
        }
    }

    // Epilogue. C frag: c0 (row g, col tc), c1 (row g, col tc+1),
    //                   c2 (row g+8, col tc), c3 (row g+8, col tc+1)
    const int g  = lane >> 2;
    const int tc = (lane & 3) * 2;

    if (is_v) {
        // write transposed into smem: st[n_local][m_local]
#pragma unroll
        for (int mf = 0; mf < 2; mf++) {
#pragma unroll
            for (int nf = 0; nf < 4; nf++) {
                int ml = wm * 32 + mf * 16 + g;
                int nl = wn * 32 + nf * 8 + tc;
                st[nl][ml]         = acc[mf][nf][0];
                st[nl + 1][ml]     = acc[mf][nf][1];
                st[nl][ml + 8]     = acc[mf][nf][2];
                st[nl + 1][ml + 8] = acc[mf][nf][3];
            }
        }
        __syncthreads();
        // coalesced out: g_WvT[b][d0+d][t0 .. t0+63]
        const int b  = tile >> 1;
        const int t0 = (tile & 1) * 64;
        const int d0 = ntile * 64;
        for (int i = tid; i < 64 * 16; i += 128) {
            int d  = i >> 4;
            int m4 = (i & 15) << 2;
            float4 val = *reinterpret_cast<const float4*>(&st[d][m4]);
            *reinterpret_cast<float4*>(
                g_WvT + ((size_t)(b * PD + d0 + d) << 7) + t0 + m4) = val;
        }
    } else {
#pragma unroll
        for (int mf = 0; mf < 2; mf++) {
            int row = (tile - 32) * 64 + wm * 32 + mf * 16 + g;
#pragma unroll
            for (int nf = 0; nf < 4; nf++) {
                int col = ntile * 64 + wn * 32 + nf * 8 + tc;
                float b0 = __ldg(bias + col);
                float b1 = __ldg(bias + col + 1);
                float2 o0 = make_float2(acc[mf][nf][0] + b0, acc[mf][nf][1] + b1);
                float2 o1 = make_float2(acc[mf][nf][2] + b0, acc[mf][nf][3] + b1);
                *reinterpret_cast<float2*>(g_Uhb + (size_t)row * PD + col)       = o0;
                *reinterpret_cast<float2*>(g_Uhb + (size_t)(row + 8) * PD + col) = o1;
            }
        }
    }
}

// ---------------------------------------------------------------------------
// Scores + softmax. Grid (TH/4=16, B=16) = 256 CTAs, 512 threads.
// Thread = (si = tid>>7 in [0,4), t = tid&127). Serial d-loop, 1 MUFU/elem.
// ---------------------------------------------------------------------------
__global__ __launch_bounds__(512) void scores_kernel(
    const float* __restrict__ wvec, float* __restrict__ beta)
{
    const int b = blockIdx.y;
    const int s0 = blockIdx.x * 4;
    const int tid = threadIdx.x;
    const int t = tid & 127;
    const int si = tid >> 7;

    __shared__ float su[4][PD];
    __shared__ float sw[PD];
    __shared__ float rmax[4][4];
    __shared__ float rsum[4][4];

    if (tid < PD) sw[tid] = wvec[tid];
    for (int i = tid; i < 4 * PD; i += 512)
        su[i >> 8][i & 255] = g_Uhb[((size_t)(b * PTH + s0 + (i >> 8)) << 8) + (i & 255)];
    __syncthreads();

    const float* wvt = g_WvT + ((size_t)b << 15) + t;   // stride 128 per d

    float acc = 0.0f;
#pragma unroll 8
    for (int d = 0; d < PD; d++) {
        float x = su[si][d] + wvt[(size_t)d << 7];
        acc += sw[d] * tanh_approx(x);
    }

    const int lane = t & 31;
    const int wq = t >> 5;

    float m = acc;
#pragma unroll
    for (int off = 16; off; off >>= 1)
        m = fmaxf(m, __shfl_xor_sync(0xffffffffu, m, off));
    if (lane == 0) rmax[si][wq] = m;
    __syncthreads();
    m = fmaxf(fmaxf(rmax[si][0], rmax[si][1]), fmaxf(rmax[si][2], rmax[si][3]));

    float e = __expf(acc - m);
    float ssum = e;
#pragma unroll
    for (int off = 16; off; off >>= 1)
        ssum += __shfl_xor_sync(0xffffffffu, ssum, off);
    if (lane == 0) rsum[si][wq] = ssum;
    __syncthreads();
    float total = (rsum[si][0] + rsum[si][1]) + (rsum[si][2] + rsum[si][3]);

    beta[((size_t)(b * PTH + s0 + si) << 7) + t] = e * (1.0f / total);
}

// ---------------------------------------------------------------------------
// Context: u[b][s][f] = sum_t beta[b][s][t] * v[b][t][f]
// Grid (4, 4, 16), 256 threads.
// ---------------------------------------------------------------------------
__global__ __launch_bounds__(256) void context_kernel(
    const float* __restrict__ v, const float* __restrict__ beta,
    float* __restrict__ u)
{
    const int b = blockIdx.z;
    const int s0 = blockIdx.y * 16;
    const int f0 = blockIdx.x * 128;
    const int tid = threadIdx.x;

    __shared__ float sb[16][PTV];

    {
        const float4* src = reinterpret_cast<const float4*>(beta + ((size_t)(b * PTH + s0) << 7));
        float4* dst = reinterpret_cast<float4*>(&sb[0][0]);
#pragma unroll
        for (int i = tid; i < 16 * PTV / 4; i += 256) dst[i] = src[i];
    }
    __syncthreads();

    const int f4 = tid & 31;
    const int row = tid >> 5;
    const int sA = row << 1;
    const int sB = sA + 1;

    float4 a0 = make_float4(0.f, 0.f, 0.f, 0.f);
    float4 a1 = make_float4(0.f, 0.f, 0.f, 0.f);

    const float* vb = v + (size_t)(b * PTV) * PF + f0 + (f4 << 2);
#pragma unroll 4
    for (int tt = 0; tt < PTV; tt++) {
        float4 vr = *reinterpret_cast<const float4*>(vb + (size_t)tt * PF);
        float b0 = sb[sA][tt];
        float b1 = sb[sB][tt];
        a0.x += b0 * vr.x; a0.y += b0 * vr.y; a0.z += b0 * vr.z; a0.w += b0 * vr.w;
        a1.x += b1 * vr.x; a1.y += b1 * vr.y; a1.z += b1 * vr.z; a1.w += b1 * vr.w;
    }

    float* ub = u + (size_t)(b * PTH + s0 + sA) * PF + f0 + (f4 << 2);
    *reinterpret_cast<float4*>(ub)      = a0;
    *reinterpret_cast<float4*>(ub + PF) = a1;
}

// ---------------------------------------------------------------------------
// kernel_launch
// Inputs: v [16,128,512], h [16,64,512], W [512,256], U [512,256], b [256], w [256,1]
// Output: u [16,64,512] float32
// ---------------------------------------------------------------------------
extern "C" void kernel_launch(void* const* d_in, const int* in_sizes, int n_in,
                              void* d_out, int out_size)
{
    const float* v    = (const float*)d_in[0];
    const float* h    = (const float*)d_in[1];
    const float* W    = (const float*)d_in[2];
    const float* U    = (const float*)d_in[3];
    const float* bvec = (const float*)d_in[4];
    const float* wvec = (const float*)d_in[5];
    float* out = (float*)d_out;

    float* beta_ptr; cudaGetSymbolAddress((void**)&beta_ptr, g_beta);

    prep_kernel<<<1024, 256>>>(v, h, W, U);
    mma_gemm_kernel<<<192, 128>>>(bvec);
    scores_kernel<<<dim3(PTH / 4, PB), 512>>>(wvec, beta_ptr);
    context_kernel<<<dim3(PF / 128, PTH / 16, PB), 256>>>(v, beta_ptr, out);
}